// round 3
// baseline (speedup 1.0000x reference)
#include <cuda_runtime.h>

// ---------------- problem constants ----------------
#define NTHREADS 224
#define NB       14          // batch rows per CTA
#define NCTA     148
#define BB       2048
#define TSTEPS   512
#define PP       17
#define HH       50
#define GG       200         // 4*H gates
#define TT       544         // T + future/P = 512 + 32
#define XW       (TSTEPS*PP) // 8704
#define OUTW     (TT*PP)     // 9248
#define KP       52          // padded hidden stride (16B-aligned float4 rows)
#define XP       20          // padded input stride

// ---------------- smem layout (float offsets) ----------------
#define OFF_W2X  0           // 200*52
#define OFF_W2H  10400
#define OFF_W3X  20800
#define OFF_W3H  31200
#define OFF_B2   41600       // 200
#define OFF_B3   41800       // 200
#define OFF_WLIN 42000       // 17*52
#define OFF_BLIN 42884       // 17 (+3 pad)
#define OFF_GS   42904       // NB*200
#define OFF_HS1  45704       // NB*52
#define OFF_HS2  46432
#define OFF_HS3  47160
#define OFF_XS   47888       // NB*20
#define SMEM_FLOATS 48168    // ~192.7 KB

__device__ __forceinline__ float fsig(float x) {
    return __fdividef(1.0f, 1.0f + __expf(-x));
}
__device__ __forceinline__ float ftanh_(float x) {
    return 2.0f * __fdividef(1.0f, 1.0f + __expf(-2.0f * x)) - 1.0f;
}

extern __shared__ float sm[];

// gates for layers 2/3: weights in smem. Each thread owns one gate row (g=tid)
// and accumulates all NB rows; activation vectors are broadcast LDS.128.
__device__ __forceinline__ void gates_smem(
    const float* __restrict__ WX, const float* __restrict__ WH,
    const float* __restrict__ Hin, const float* __restrict__ Hsame,
    const float* __restrict__ Bsm, float* __restrict__ GS, int tid)
{
    const int g = (tid < GG) ? tid : 0;   // tid>=200: duplicate gate 0, discarded
    float acc[NB];
    const float bg = Bsm[g];
#pragma unroll
    for (int r = 0; r < NB; r++) acc[r] = bg;

    for (int kk = 0; kk < KP; kk += 4) {
        float4 wx = *(const float4*)(WX + g * KP + kk);
        float4 wh = *(const float4*)(WH + g * KP + kk);
#pragma unroll
        for (int r = 0; r < NB; r++) {
            float4 a = *(const float4*)(Hin   + r * KP + kk);
            float4 b = *(const float4*)(Hsame + r * KP + kk);
            acc[r] = fmaf(wx.x, a.x, acc[r]);
            acc[r] = fmaf(wx.y, a.y, acc[r]);
            acc[r] = fmaf(wx.z, a.z, acc[r]);
            acc[r] = fmaf(wx.w, a.w, acc[r]);
            acc[r] = fmaf(wh.x, b.x, acc[r]);
            acc[r] = fmaf(wh.y, b.y, acc[r]);
            acc[r] = fmaf(wh.z, b.z, acc[r]);
            acc[r] = fmaf(wh.w, b.w, acc[r]);
        }
    }
    if (tid < GG) {
#pragma unroll
        for (int r = 0; r < NB; r++) GS[r * GG + tid] = acc[r];
    }
}

// LSTM pointwise: 4 work items per thread cover NB*H = 700 outputs.
__device__ __forceinline__ void act_layer(
    const float* __restrict__ GS, float* __restrict__ Hdst,
    float (&c)[4], const int (&ar)[4], const int (&aj)[4], const bool (&av)[4])
{
#pragma unroll
    for (int q = 0; q < 4; q++) {
        if (av[q]) {
            int base = ar[q] * GG + aj[q];
            float xi = GS[base];
            float xf = GS[base + HH];
            float xg = GS[base + 2 * HH];
            float xo = GS[base + 3 * HH];
            float iv = fsig(xi), fv = fsig(xf), gv = ftanh_(xg), ov = fsig(xo);
            float cn = fmaf(fv, c[q], iv * gv);
            c[q] = cn;
            Hdst[ar[q] * KP + aj[q]] = ov * ftanh_(cn);
        }
    }
}

__global__ void __launch_bounds__(NTHREADS, 1)
lstm_forward(const float* __restrict__ x,
             const float* __restrict__ Wih1, const float* __restrict__ Whh1,
             const float* __restrict__ bih1, const float* __restrict__ bhh1,
             const float* __restrict__ Wih2, const float* __restrict__ Whh2,
             const float* __restrict__ bih2, const float* __restrict__ bhh2,
             const float* __restrict__ Wih3, const float* __restrict__ Whh3,
             const float* __restrict__ bih3, const float* __restrict__ bhh3,
             const float* __restrict__ Wlin, const float* __restrict__ blin,
             float* __restrict__ out)
{
    const int tid  = threadIdx.x;
    const int row0 = blockIdx.x * NB;

    // ---- cooperative weight load (layers 2,3 + head) into smem, zero-padded ----
    for (int idx = tid; idx < GG * KP; idx += NTHREADS) {
        int g = idx / KP, k = idx - g * KP;
        bool v = (k < HH);
        int src = g * HH + k;
        sm[OFF_W2X + idx] = v ? Wih2[src] : 0.f;
        sm[OFF_W2H + idx] = v ? Whh2[src] : 0.f;
        sm[OFF_W3X + idx] = v ? Wih3[src] : 0.f;
        sm[OFF_W3H + idx] = v ? Whh3[src] : 0.f;
    }
    for (int idx = tid; idx < GG; idx += NTHREADS) {
        sm[OFF_B2 + idx] = bih2[idx] + bhh2[idx];
        sm[OFF_B3 + idx] = bih3[idx] + bhh3[idx];
    }
    for (int idx = tid; idx < PP * KP; idx += NTHREADS) {
        int p = idx / KP, k = idx - p * KP;
        sm[OFF_WLIN + idx] = (k < HH) ? Wlin[p * HH + k] : 0.f;
    }
    if (tid < PP) sm[OFF_BLIN + tid] = blin[tid];
    // zero h-state (3 contiguous buffers) and padded input staging
    for (int idx = tid; idx < 3 * NB * KP; idx += NTHREADS) sm[OFF_HS1 + idx] = 0.f;
    for (int idx = tid; idx < NB * XP; idx += NTHREADS)     sm[OFF_XS  + idx] = 0.f;

    // ---- layer-1 weights live in registers (67 real + pad) ----
    float w1x[XP], w1h[KP], bg1;
    {
        const int g = (tid < GG) ? tid : 0;
#pragma unroll
        for (int k = 0; k < XP; k++) w1x[k] = (k < PP) ? Wih1[g * PP + k] : 0.f;
#pragma unroll
        for (int k = 0; k < KP; k++) w1h[k] = (k < HH) ? Whh1[g * HH + k] : 0.f;
        bg1 = bih1[g] + bhh1[g];
    }

    // ---- static per-thread work-item maps ----
    int ar[4], aj[4]; bool av[4];              // activation items (NB*H = 700)
#pragma unroll
    for (int q = 0; q < 4; q++) {
        int it = tid + q * NTHREADS;
        av[q] = (it < NB * HH);
        int r = it / HH;
        ar[q] = r; aj[q] = it - r * HH;
    }
    int orr[2], op[2]; bool ov[2];             // output / x-load items (NB*P = 238)
#pragma unroll
    for (int q = 0; q < 2; q++) {
        int it = tid + q * NTHREADS;
        ov[q] = (it < NB * PP);
        int r = it / PP;
        orr[q] = r; op[q] = it - r * PP;
    }
    float c1[4] = {0.f,0.f,0.f,0.f};
    float c2[4] = {0.f,0.f,0.f,0.f};
    float c3[4] = {0.f,0.f,0.f,0.f};

    // ---- prefetch x for t=0 into registers ----
    float xreg[2] = {0.f, 0.f};
#pragma unroll
    for (int q = 0; q < 2; q++) {
        if (ov[q]) {
            int brow = row0 + orr[q];
            if (brow < BB) xreg[q] = x[(size_t)brow * XW + op[q]];
        }
    }
    __syncthreads();

    // ================= time loop =================
    for (int t = 0; t < TT; t++) {
        // stage this step's input (teacher-forced phase only;
        // for t>=T the previous step's output was written into XS directly)
        if (t < TSTEPS) {
#pragma unroll
            for (int q = 0; q < 2; q++)
                if (ov[q]) sm[OFF_XS + orr[q] * XP + op[q]] = xreg[q];
        }
        __syncthreads();                                   // S0: XS ready

        // prefetch next step's x (latency hidden behind this step's compute)
        if (t + 1 < TSTEPS) {
#pragma unroll
            for (int q = 0; q < 2; q++) {
                if (ov[q]) {
                    int brow = row0 + orr[q];
                    xreg[q] = (brow < BB)
                        ? x[(size_t)brow * XW + (t + 1) * PP + op[q]] : 0.f;
                }
            }
        }

        // ---- layer 1 gates: register weights, broadcast activations ----
        {
            float acc[NB];
#pragma unroll
            for (int r = 0; r < NB; r++) acc[r] = bg1;
#pragma unroll
            for (int kk = 0; kk < XP; kk += 4) {
#pragma unroll
                for (int r = 0; r < NB; r++) {
                    float4 v = *(const float4*)(sm + OFF_XS + r * XP + kk);
                    acc[r] = fmaf(w1x[kk    ], v.x, acc[r]);
                    acc[r] = fmaf(w1x[kk + 1], v.y, acc[r]);
                    acc[r] = fmaf(w1x[kk + 2], v.z, acc[r]);
                    acc[r] = fmaf(w1x[kk + 3], v.w, acc[r]);
                }
            }
#pragma unroll
            for (int kk = 0; kk < KP; kk += 4) {
#pragma unroll
                for (int r = 0; r < NB; r++) {
                    float4 v = *(const float4*)(sm + OFF_HS1 + r * KP + kk);
                    acc[r] = fmaf(w1h[kk    ], v.x, acc[r]);
                    acc[r] = fmaf(w1h[kk + 1], v.y, acc[r]);
                    acc[r] = fmaf(w1h[kk + 2], v.z, acc[r]);
                    acc[r] = fmaf(w1h[kk + 3], v.w, acc[r]);
                }
            }
            if (tid < GG) {
#pragma unroll
                for (int r = 0; r < NB; r++) sm[OFF_GS + r * GG + tid] = acc[r];
            }
        }
        __syncthreads();                                   // S1
        act_layer(sm + OFF_GS, sm + OFF_HS1, c1, ar, aj, av);
        __syncthreads();                                   // S2

        gates_smem(sm + OFF_W2X, sm + OFF_W2H, sm + OFF_HS1, sm + OFF_HS2,
                   sm + OFF_B2, sm + OFF_GS, tid);
        __syncthreads();                                   // S3
        act_layer(sm + OFF_GS, sm + OFF_HS2, c2, ar, aj, av);
        __syncthreads();                                   // S4

        gates_smem(sm + OFF_W3X, sm + OFF_W3H, sm + OFF_HS2, sm + OFF_HS3,
                   sm + OFF_B3, sm + OFF_GS, tid);
        __syncthreads();                                   // S5
        act_layer(sm + OFF_GS, sm + OFF_HS3, c3, ar, aj, av);
        __syncthreads();                                   // S6

        // ---- linear head + output store (+ feed back as next input) ----
#pragma unroll
        for (int q = 0; q < 2; q++) {
            if (ov[q]) {
                int r = orr[q], p = op[q];
                float acc = sm[OFF_BLIN + p];
#pragma unroll
                for (int kk = 0; kk < KP; kk += 4) {
                    float4 w = *(const float4*)(sm + OFF_WLIN + p * KP + kk);
                    float4 h = *(const float4*)(sm + OFF_HS3  + r * KP + kk);
                    acc = fmaf(w.x, h.x, acc);
                    acc = fmaf(w.y, h.y, acc);
                    acc = fmaf(w.z, h.z, acc);
                    acc = fmaf(w.w, h.w, acc);
                }
                int brow = row0 + r;
                if (brow < BB) out[(size_t)brow * OUTW + t * PP + p] = acc;
                if (t >= TSTEPS - 1) sm[OFF_XS + r * XP + p] = acc; // autoregressive feed
            }
        }
        // next-iteration S0 orders XS writes vs. layer-1 reads
    }
}

extern "C" void kernel_launch(void* const* d_in, const int* in_sizes, int n_in,
                              void* d_out, int out_size)
{
    const float* x    = (const float*)d_in[0];
    const float* Wih1 = (const float*)d_in[1];
    const float* Whh1 = (const float*)d_in[2];
    const float* bih1 = (const float*)d_in[3];
    const float* bhh1 = (const float*)d_in[4];
    const float* Wih2 = (const float*)d_in[5];
    const float* Whh2 = (const float*)d_in[6];
    const float* bih2 = (const float*)d_in[7];
    const float* bhh2 = (const float*)d_in[8];
    const float* Wih3 = (const float*)d_in[9];
    const float* Whh3 = (const float*)d_in[10];
    const float* bih3 = (const float*)d_in[11];
    const float* bhh3 = (const float*)d_in[12];
    const float* Wlin = (const float*)d_in[13];
    const float* blin = (const float*)d_in[14];
    float* out = (float*)d_out;

    const size_t smem = (size_t)SMEM_FLOATS * sizeof(float);
    cudaFuncSetAttribute(lstm_forward,
                         cudaFuncAttributeMaxDynamicSharedMemorySize, (int)smem);
    lstm_forward<<<NCTA, NTHREADS, smem>>>(
        x, Wih1, Whh1, bih1, bhh1, Wih2, Whh2, bih2, bhh2,
        Wih3, Whh3, bih3, bhh3, Wlin, blin, out);
}